// round 12
// baseline (speedup 1.0000x reference)
#include <cuda_runtime.h>
#include <math.h>

// ConvolutionalCapsule EM routing — fused, transposed weights, paired i-steps,
// expanded Mahalanobis (q = sum v*(iv*v + nB) + C), fixed-shift softmax,
// 2-warp CTAs at occupancy 8 (minimal barrier coupling, single wave).
// Shapes: pose [4,14,14,32,4,4], act [4,14,14,32], w [1,288,32,4,4],
//         beta_v/beta_a [1,1,1,32]; stride=1, routings=3.
// Output: pose [4,12,12,32,4,4] then activation [4,12,12,32]

#define EPSF 1e-9f

namespace {
constexpr int S   = 12;
constexpr int IC  = 32;
constexpr int O   = 32;
constexpr int I   = 288;   // 3*3*32
constexpr int PR  = 16;
constexpr int NW  = 2;     // warps per block; 144 i's per warp -> 72 pairs
constexpr int NT  = 32 * NW;
constexpr int PAD = 17;
constexpr int POSE_OUT = 4 * S * S * O * PR;
constexpr float SHIFT = 44.0f;   // exp(zz+44): zz<=0 -> no overflow, exact ratio
}

// Transposed weights: g_wt[(i*4 + q)*32 + o] = { w[i,o,q,0..3] }
__device__ float4 g_wt[I * 4 * O];

__global__ void transpose_w_kernel(const float* __restrict__ w)
{
    int idx = blockIdx.x * blockDim.x + threadIdx.x;
    if (idx >= I * O * 4) return;
    const float4* w4 = reinterpret_cast<const float4*>(w);
    int q = idx & 3;
    int o = (idx >> 2) & 31;
    int i = idx >> 7;
    g_wt[(i * 4 + q) * 32 + o] = w4[idx];
}

// votes v[p*4+r] = sum_q pose[i,p,q] * w_t[i,q][o].r
__device__ __forceinline__ void compute_votes(const float4* __restrict__ pp,
                                              const float4* __restrict__ wt,
                                              float v[PR])
{
    float4 W0 = wt[0], W1 = wt[32], W2 = wt[64], W3 = wt[96];
    #pragma unroll
    for (int p = 0; p < 4; p++) {
        float4 P = pp[p];
        v[p*4+0] = fmaf(P.x, W0.x, fmaf(P.y, W1.x, fmaf(P.z, W2.x, P.w * W3.x)));
        v[p*4+1] = fmaf(P.x, W0.y, fmaf(P.y, W1.y, fmaf(P.z, W2.y, P.w * W3.y)));
        v[p*4+2] = fmaf(P.x, W0.z, fmaf(P.y, W1.z, fmaf(P.z, W2.z, P.w * W3.z)));
        v[p*4+3] = fmaf(P.x, W0.w, fmaf(P.y, W1.w, fmaf(P.z, W2.w, P.w * W3.w)));
    }
}

__global__ __launch_bounds__(NT, 8)
void capsule_em_kernel(const float* __restrict__ pose_in,
                       const float* __restrict__ act_in,
                       const float* __restrict__ beta_v,
                       const float* __restrict__ beta_a,
                       float* __restrict__ out)
{
    __shared__ float sh_pose[I * PR];
    __shared__ float sh_act[I];
    __shared__ float sS1[O * PAD];
    __shared__ float sS2[O * PAD];
    __shared__ float sS0[O];

    const int o   = threadIdx.x;       // lane = output capsule
    const int wy  = threadIdx.y;       // warp id (0..1)
    const int tid = wy * 32 + o;

    const int n   = blockIdx.x;
    const int b   = n / (S * S);
    const int rem = n % (S * S);
    const int oh  = rem / S;
    const int ow  = rem % S;

    // ---- load receptive field into SMEM ----
    {
        float4* dst4 = reinterpret_cast<float4*>(sh_pose);
        const float4* src4 = reinterpret_cast<const float4*>(pose_in);
        #pragma unroll 1
        for (int idx = tid; idx < I * 4; idx += NT) {
            int i  = idx >> 2, f = idx & 3;
            int k  = i >> 5,  ic = i & 31;
            int kh = k / 3,   kw = k % 3;
            long g = ((long)((b * 14 + oh + kh) * 14 + (ow + kw)) * IC + ic) * 4 + f;
            dst4[idx] = src4[g];
        }
        #pragma unroll 1
        for (int idx = tid; idx < I; idx += NT) {
            int k  = idx >> 5, ic = idx & 31;
            int kh = k / 3,    kw = k % 3;
            sh_act[idx] = act_in[((b * 14 + oh + kh) * 14 + (ow + kw)) * IC + ic];
        }
    }
    const float bv = beta_v[o];
    const float ba = beta_a[o];
    __syncthreads();

    // per-o expanded-quadratic constants: q = sum_e v*(ivr*v + nB) + C
    float ivr[PR], nB[PR];
    #pragma unroll
    for (int e = 0; e < PR; e++) { ivr[e] = 0.f; nB[e] = 0.f; }
    float Co2 = 0.f, act_o = 0.f;     // Co2 = Co - C

    #pragma unroll 1
    for (int it = 0; it < 3; ++it) {
        #pragma unroll 1
        for (int k2 = tid; k2 < O * PAD; k2 += NT) { sS1[k2] = 0.f; sS2[k2] = 0.f; }
        if (tid < O) sS0[tid] = 0.f;
        __syncthreads();

        float s0 = 0.f, s1[PR], s2[PR];
        #pragma unroll
        for (int e = 0; e < PR; e++) { s1[e] = 0.f; s2[e] = 0.f; }

        if (it == 0) {
            // uniform rr (1/32 folded into M-step): no softmax chain
            #pragma unroll 1
            for (int ii = 0; ii < I / NW; ii += 2) {
                const int ia = wy + ii * NW;
                const int ib = ia + NW;
                float va[PR], vb[PR];
                compute_votes(reinterpret_cast<const float4*>(sh_pose) + (ia << 2),
                              g_wt + ia * 128 + o, va);
                compute_votes(reinterpret_cast<const float4*>(sh_pose) + (ib << 2),
                              g_wt + ib * 128 + o, vb);
                float rpa = sh_act[ia];
                float rpb = sh_act[ib];
                s0 += rpa + rpb;
                #pragma unroll
                for (int e = 0; e < PR; e++) {
                    float ta = rpa * va[e];
                    float tb = rpb * vb[e];
                    s1[e] += ta + tb;
                    s2[e] = fmaf(ta, va[e], fmaf(tb, vb[e], s2[e]));
                }
            }
        } else {
            #pragma unroll 1
            for (int ii = 0; ii < I / NW; ii += 2) {
                const int ia = wy + ii * NW;
                const int ib = ia + NW;
                float aa = sh_act[ia];
                float ab = sh_act[ib];

                float va[PR], vb[PR];
                compute_votes(reinterpret_cast<const float4*>(sh_pose) + (ia << 2),
                              g_wt + ia * 128 + o, va);
                compute_votes(reinterpret_cast<const float4*>(sh_pose) + (ib << 2),
                              g_wt + ib * 128 + o, vb);

                // q (expanded): 2 FMAs per element, 4-way trees
                float qa0 = 0.f, qa1 = 0.f, qa2 = 0.f, qa3 = 0.f;
                float qb0 = 0.f, qb1 = 0.f, qb2 = 0.f, qb3 = 0.f;
                #pragma unroll
                for (int e = 0; e < PR; e += 4) {
                    float u;
                    u = fmaf(ivr[e+0], va[e+0], nB[e+0]); qa0 = fmaf(va[e+0], u, qa0);
                    u = fmaf(ivr[e+1], va[e+1], nB[e+1]); qa1 = fmaf(va[e+1], u, qa1);
                    u = fmaf(ivr[e+2], va[e+2], nB[e+2]); qa2 = fmaf(va[e+2], u, qa2);
                    u = fmaf(ivr[e+3], va[e+3], nB[e+3]); qa3 = fmaf(va[e+3], u, qa3);
                    u = fmaf(ivr[e+0], vb[e+0], nB[e+0]); qb0 = fmaf(vb[e+0], u, qb0);
                    u = fmaf(ivr[e+1], vb[e+1], nB[e+1]); qb1 = fmaf(vb[e+1], u, qb1);
                    u = fmaf(ivr[e+2], vb[e+2], nB[e+2]); qb2 = fmaf(vb[e+2], u, qb2);
                    u = fmaf(ivr[e+3], vb[e+3], nB[e+3]); qb3 = fmaf(vb[e+3], u, qb3);
                }
                float zza = Co2 - ((qa0 + qa1) + (qa2 + qa3));
                float zzb = Co2 - ((qb0 + qb1) + (qb2 + qb3));

                // fixed-shift softmax over lanes, two interleaved sum chains
                float ea = __expf(zza + SHIFT);
                float eb = __expf(zzb + SHIFT);
                float sma = ea, smb = eb;
                #pragma unroll
                for (int off = 16; off; off >>= 1) {
                    sma += __shfl_xor_sync(0xffffffffu, sma, off);
                    smb += __shfl_xor_sync(0xffffffffu, smb, off);
                }
                float rpa = __fdividef(ea, sma) * aa;
                float rpb = __fdividef(eb, smb) * ab;

                s0 += rpa + rpb;
                #pragma unroll
                for (int e = 0; e < PR; e++) {
                    float ta = rpa * va[e];
                    float tb = rpb * vb[e];
                    s1[e] += ta + tb;
                    s2[e] = fmaf(ta, va[e], fmaf(tb, vb[e], s2[e]));
                }
            }
        }

        // cross-warp reduction (conflict-free padded atomics)
        atomicAdd(&sS0[o], s0);
        #pragma unroll
        for (int e = 0; e < PR; e++) {
            atomicAdd(&sS1[o * PAD + e], s1[e]);
            atomicAdd(&sS2[o * PAD + e], s2[e]);
        }
        __syncthreads();

        // M-step (replicated across the 2 warps). it==0: uniform 1/32 cancels
        // in mean/var; only rr_sum (cost term) needs the scale.
        float S0raw = sS0[o];
        float S0v   = (it == 0) ? S0raw * (1.0f / 32.0f) : S0raw;
        float invS0 = 1.0f / S0raw;
        float lsum  = 0.f, C = 0.f;
        #pragma unroll
        for (int e = 0; e < PR; e++) {
            float m   = sS1[o * PAD + e] * invS0;
            float var = fmaxf(sS2[o * PAD + e] * invS0 - m * m, 0.f);
            float sd  = sqrtf(var);
            float iv  = 0.5f / fmaxf(var, 1e-30f);
            ivr[e] = iv;
            nB[e]  = -2.0f * m * iv;
            C      = fmaf(iv * m, m, C);
            lsum  += __logf(sd + EPSF);
        }
        float cost     = (16.0f * bv + lsum) * S0v;
        float inv_temp = 1.0f + (float)it;   // 1, 2, 3
        act_o = 1.0f / (1.0f + __expf(-inv_temp * (ba - cost)));
        if (it < 2)
            Co2 = __logf(act_o + EPSF) - lsum - C;   // not needed after last pass
        __syncthreads();
    }

    // ---- write outputs (warp 0 only); means re-derived from persisted sums ----
    if (wy == 0) {
        float invS0 = 1.0f / sS0[o];
        float4* op = reinterpret_cast<float4*>(out + ((long)n * O + o) * PR);
        #pragma unroll
        for (int p = 0; p < 4; p++) {
            float4 m4;
            m4.x = sS1[o * PAD + p*4 + 0] * invS0;
            m4.y = sS1[o * PAD + p*4 + 1] * invS0;
            m4.z = sS1[o * PAD + p*4 + 2] * invS0;
            m4.w = sS1[o * PAD + p*4 + 3] * invS0;
            op[p] = m4;
        }
        out[POSE_OUT + (long)n * O + o] = act_o;
    }
}

extern "C" void kernel_launch(void* const* d_in, const int* in_sizes, int n_in,
                              void* d_out, int out_size)
{
    const float* pose_in = (const float*)d_in[0];
    const float* act_in  = (const float*)d_in[1];
    const float* w       = (const float*)d_in[2];
    const float* beta_v  = (const float*)d_in[3];
    const float* beta_a  = (const float*)d_in[4];
    float* out = (float*)d_out;

    transpose_w_kernel<<<(I * O * 4 + 255) / 256, 256>>>(w);

    dim3 grid(4 * S * S);
    dim3 block(32, NW);
    capsule_em_kernel<<<grid, block>>>(pose_in, act_in, beta_v, beta_a, out);
}

// round 13
// speedup vs baseline: 1.4028x; 1.4028x over previous
#include <cuda_runtime.h>
#include <math.h>

// ConvolutionalCapsule EM routing — fused, transposed weights, paired i-steps,
// expanded Mahalanobis, fixed-shift softmax, 4-warp CTAs @ occ 4 (R11 base).
// R13: atomic reduction -> per-warp smem partials (33 STS vs 33 spread-ATOMS),
//      reduction folded into the replicated M-step; 32 MUFU (sqrt+log per e)
//      -> 2 logs via 0.5*log(prod var).
// Shapes: pose [4,14,14,32,4,4], act [4,14,14,32], w [1,288,32,4,4],
//         beta_v/beta_a [1,1,1,32]; stride=1, routings=3.
// Output: pose [4,12,12,32,4,4] then activation [4,12,12,32]

#define EPSF 1e-9f

namespace {
constexpr int S   = 12;
constexpr int IC  = 32;
constexpr int O   = 32;
constexpr int I   = 288;   // 3*3*32
constexpr int PR  = 16;
constexpr int NW  = 4;     // warps per block; 72 i's per warp -> 36 pairs
constexpr int NT  = 32 * NW;
constexpr int PAD = 17;    // conflict-free lane stride
constexpr int POSE_OUT = 4 * S * S * O * PR;
constexpr float SHIFT = 44.0f;   // exp(zz+44): zz<=0 -> no overflow, exact ratio
}

// Transposed weights: g_wt[(i*4 + q)*32 + o] = { w[i,o,q,0..3] }
__device__ float4 g_wt[I * 4 * O];

__global__ void transpose_w_kernel(const float* __restrict__ w)
{
    int idx = blockIdx.x * blockDim.x + threadIdx.x;
    if (idx >= I * O * 4) return;
    const float4* w4 = reinterpret_cast<const float4*>(w);
    int q = idx & 3;
    int o = (idx >> 2) & 31;
    int i = idx >> 7;
    g_wt[(i * 4 + q) * 32 + o] = w4[idx];
}

// votes v[p*4+r] = sum_q pose[i,p,q] * w_t[i,q][o].r
__device__ __forceinline__ void compute_votes(const float4* __restrict__ pp,
                                              const float4* __restrict__ wt,
                                              float v[PR])
{
    float4 W0 = wt[0], W1 = wt[32], W2 = wt[64], W3 = wt[96];
    #pragma unroll
    for (int p = 0; p < 4; p++) {
        float4 P = pp[p];
        v[p*4+0] = fmaf(P.x, W0.x, fmaf(P.y, W1.x, fmaf(P.z, W2.x, P.w * W3.x)));
        v[p*4+1] = fmaf(P.x, W0.y, fmaf(P.y, W1.y, fmaf(P.z, W2.y, P.w * W3.y)));
        v[p*4+2] = fmaf(P.x, W0.z, fmaf(P.y, W1.z, fmaf(P.z, W2.z, P.w * W3.z)));
        v[p*4+3] = fmaf(P.x, W0.w, fmaf(P.y, W1.w, fmaf(P.z, W2.w, P.w * W3.w)));
    }
}

__global__ __launch_bounds__(NT, 4)
void capsule_em_kernel(const float* __restrict__ pose_in,
                       const float* __restrict__ act_in,
                       const float* __restrict__ beta_v,
                       const float* __restrict__ beta_a,
                       float* __restrict__ out)
{
    __shared__ float sh_pose[I * PR];
    __shared__ float sh_act[I];
    __shared__ float sP0[NW][O];          // per-warp partial S0
    __shared__ float sP1[NW][O * PAD];    // per-warp partial S1 (stride 17)
    __shared__ float sP2[NW][O * PAD];    // per-warp partial S2

    const int o   = threadIdx.x;       // lane = output capsule
    const int wy  = threadIdx.y;       // warp id (0..3)
    const int tid = wy * 32 + o;

    const int n   = blockIdx.x;
    const int b   = n / (S * S);
    const int rem = n % (S * S);
    const int oh  = rem / S;
    const int ow  = rem % S;

    // ---- load receptive field into SMEM ----
    {
        float4* dst4 = reinterpret_cast<float4*>(sh_pose);
        const float4* src4 = reinterpret_cast<const float4*>(pose_in);
        #pragma unroll 1
        for (int idx = tid; idx < I * 4; idx += NT) {
            int i  = idx >> 2, f = idx & 3;
            int k  = i >> 5,  ic = i & 31;
            int kh = k / 3,   kw = k % 3;
            long g = ((long)((b * 14 + oh + kh) * 14 + (ow + kw)) * IC + ic) * 4 + f;
            dst4[idx] = src4[g];
        }
        #pragma unroll 1
        for (int idx = tid; idx < I; idx += NT) {
            int k  = idx >> 5, ic = idx & 31;
            int kh = k / 3,    kw = k % 3;
            sh_act[idx] = act_in[((b * 14 + oh + kh) * 14 + (ow + kw)) * IC + ic];
        }
    }
    const float bv = beta_v[o];
    const float ba = beta_a[o];
    __syncthreads();

    // per-o expanded-quadratic constants: q = sum_e v*(ivr*v + nB) + C
    float ivr[PR], nB[PR];
    #pragma unroll
    for (int e = 0; e < PR; e++) { ivr[e] = 0.f; nB[e] = 0.f; }
    float Co2 = 0.f, act_o = 0.f;     // Co2 = Co - C

    #pragma unroll 1
    for (int it = 0; it < 3; ++it) {
        float s0 = 0.f, s1[PR], s2[PR];
        #pragma unroll
        for (int e = 0; e < PR; e++) { s1[e] = 0.f; s2[e] = 0.f; }

        if (it == 0) {
            // uniform rr (1/32 folded into M-step): no softmax chain
            #pragma unroll 1
            for (int ii = 0; ii < I / NW; ii += 2) {
                const int ia = wy + ii * NW;
                const int ib = ia + NW;
                float va[PR], vb[PR];
                compute_votes(reinterpret_cast<const float4*>(sh_pose) + (ia << 2),
                              g_wt + ia * 128 + o, va);
                compute_votes(reinterpret_cast<const float4*>(sh_pose) + (ib << 2),
                              g_wt + ib * 128 + o, vb);
                float rpa = sh_act[ia];
                float rpb = sh_act[ib];
                s0 += rpa + rpb;
                #pragma unroll
                for (int e = 0; e < PR; e++) {
                    float ta = rpa * va[e];
                    float tb = rpb * vb[e];
                    s1[e] += ta + tb;
                    s2[e] = fmaf(ta, va[e], fmaf(tb, vb[e], s2[e]));
                }
            }
        } else {
            #pragma unroll 1
            for (int ii = 0; ii < I / NW; ii += 2) {
                const int ia = wy + ii * NW;
                const int ib = ia + NW;
                float aa = sh_act[ia];
                float ab = sh_act[ib];

                float va[PR], vb[PR];
                compute_votes(reinterpret_cast<const float4*>(sh_pose) + (ia << 2),
                              g_wt + ia * 128 + o, va);
                compute_votes(reinterpret_cast<const float4*>(sh_pose) + (ib << 2),
                              g_wt + ib * 128 + o, vb);

                // q (expanded): 2 FMAs per element, 4-way trees
                float qa0 = 0.f, qa1 = 0.f, qa2 = 0.f, qa3 = 0.f;
                float qb0 = 0.f, qb1 = 0.f, qb2 = 0.f, qb3 = 0.f;
                #pragma unroll
                for (int e = 0; e < PR; e += 4) {
                    float u;
                    u = fmaf(ivr[e+0], va[e+0], nB[e+0]); qa0 = fmaf(va[e+0], u, qa0);
                    u = fmaf(ivr[e+1], va[e+1], nB[e+1]); qa1 = fmaf(va[e+1], u, qa1);
                    u = fmaf(ivr[e+2], va[e+2], nB[e+2]); qa2 = fmaf(va[e+2], u, qa2);
                    u = fmaf(ivr[e+3], va[e+3], nB[e+3]); qa3 = fmaf(va[e+3], u, qa3);
                    u = fmaf(ivr[e+0], vb[e+0], nB[e+0]); qb0 = fmaf(vb[e+0], u, qb0);
                    u = fmaf(ivr[e+1], vb[e+1], nB[e+1]); qb1 = fmaf(vb[e+1], u, qb1);
                    u = fmaf(ivr[e+2], vb[e+2], nB[e+2]); qb2 = fmaf(vb[e+2], u, qb2);
                    u = fmaf(ivr[e+3], vb[e+3], nB[e+3]); qb3 = fmaf(vb[e+3], u, qb3);
                }
                float zza = Co2 - ((qa0 + qa1) + (qa2 + qa3));
                float zzb = Co2 - ((qb0 + qb1) + (qb2 + qb3));

                // fixed-shift softmax over lanes, two interleaved sum chains
                float ea = __expf(zza + SHIFT);
                float eb = __expf(zzb + SHIFT);
                float sma = ea, smb = eb;
                #pragma unroll
                for (int off = 16; off; off >>= 1) {
                    sma += __shfl_xor_sync(0xffffffffu, sma, off);
                    smb += __shfl_xor_sync(0xffffffffu, smb, off);
                }
                float rpa = __fdividef(ea, sma) * aa;
                float rpb = __fdividef(eb, smb) * ab;

                s0 += rpa + rpb;
                #pragma unroll
                for (int e = 0; e < PR; e++) {
                    float ta = rpa * va[e];
                    float tb = rpb * vb[e];
                    s1[e] += ta + tb;
                    s2[e] = fmaf(ta, va[e], fmaf(tb, vb[e], s2[e]));
                }
            }
        }

        // per-warp partials -> smem (conflict-free stride-17 STS; no atomics,
        // no zeroing pass needed: every slot is overwritten)
        sP0[wy][o] = s0;
        #pragma unroll
        for (int e = 0; e < PR; e++) {
            sP1[wy][o * PAD + e] = s1[e];
            sP2[wy][o * PAD + e] = s2[e];
        }
        __syncthreads();

        // M-step (replicated across warps), 4-way reduction folded in.
        // it==0: uniform 1/32 cancels in mean/var; only rr_sum needs the scale.
        float S0raw = (sP0[0][o] + sP0[1][o]) + (sP0[2][o] + sP0[3][o]);
        float S0v   = (it == 0) ? S0raw * (1.0f / 32.0f) : S0raw;
        float invS0 = 1.0f / S0raw;
        float C = 0.f;
        float pv0 = 1.f, pv1 = 1.f, pv2 = 1.f, pv3 = 1.f;   // var products
        #pragma unroll
        for (int e = 0; e < PR; e++) {
            float S1e = (sP1[0][o * PAD + e] + sP1[1][o * PAD + e])
                      + (sP1[2][o * PAD + e] + sP1[3][o * PAD + e]);
            float S2e = (sP2[0][o * PAD + e] + sP2[1][o * PAD + e])
                      + (sP2[2][o * PAD + e] + sP2[3][o * PAD + e]);
            float m   = S1e * invS0;
            float var = fmaxf(S2e * invS0 - m * m, 1e-18f);
            float iv  = 0.5f / var;
            ivr[e] = iv;
            nB[e]  = -2.0f * m * iv;
            C      = fmaf(iv * m, m, C);
            if      (e < 4)  pv0 *= var;
            else if (e < 8)  pv1 *= var;
            else if (e < 12) pv2 *= var;
            else             pv3 *= var;
        }
        // sum log(sd+eps) ~= 0.5*log(prod var)  (eps shift negligible, vars clamped)
        float lsum = 0.5f * (__logf(pv0 * pv1) + __logf(pv2 * pv3));
        float cost     = (16.0f * bv + lsum) * S0v;
        float inv_temp = 1.0f + (float)it;   // 1, 2, 3
        act_o = 1.0f / (1.0f + __expf(-inv_temp * (ba - cost)));
        if (it < 2)
            Co2 = __logf(act_o + EPSF) - lsum - C;   // unused after last pass
        __syncthreads();   // protect sP* from next pass's overwrites
    }

    // ---- write outputs (warp 0 only); means re-derived from partials ----
    if (wy == 0) {
        float S0raw = (sP0[0][o] + sP0[1][o]) + (sP0[2][o] + sP0[3][o]);
        float invS0 = 1.0f / S0raw;
        float4* op = reinterpret_cast<float4*>(out + ((long)n * O + o) * PR);
        #pragma unroll
        for (int p = 0; p < 4; p++) {
            float4 m4;
            float* r = &m4.x;
            #pragma unroll
            for (int c = 0; c < 4; c++) {
                int e = p * 4 + c;
                r[c] = ((sP1[0][o * PAD + e] + sP1[1][o * PAD + e])
                      + (sP1[2][o * PAD + e] + sP1[3][o * PAD + e])) * invS0;
            }
            op[p] = m4;
        }
        out[POSE_OUT + (long)n * O + o] = act_o;
    }
}

extern "C" void kernel_launch(void* const* d_in, const int* in_sizes, int n_in,
                              void* d_out, int out_size)
{
    const float* pose_in = (const float*)d_in[0];
    const float* act_in  = (const float*)d_in[1];
    const float* w       = (const float*)d_in[2];
    const float* beta_v  = (const float*)d_in[3];
    const float* beta_a  = (const float*)d_in[4];
    float* out = (float*)d_out;

    transpose_w_kernel<<<(I * O * 4 + 255) / 256, 256>>>(w);

    dim3 grid(4 * S * S);
    dim3 block(32, NW);
    capsule_em_kernel<<<grid, block>>>(pose_in, act_in, beta_v, beta_a, out);
}